// round 5
// baseline (speedup 1.0000x reference)
#include <cuda_runtime.h>

// DenseQConv1D analytic collapse (exact):
//   out[b,c,l] = cos(theta[c,0]) * (S_even - S_odd) / max(S_total, 1e-24)
//   with S_* = windowed 8-tap sums of a[b,l] = sum_cin x[b,cin,l]^2.
// Derivation: out = s^T (E R) S (E R)^T s ; R S R^T = H(theta0) (x) I^8 ;
// E = CNOT-ring permutation (linear over GF(2)); conjugated M_c is
// diag(+/-cos(theta[c,0])) on the 128-dim patch support, sign = (-1)^(j&1).
//
// R5: minimum-grid extreme — 8 CTAs (one per batch) x 1024 threads.
//     No halo: thread tid owns a[tid] over the full L=1024, window
//     a[tid..tid+7] is CTA-local. Tests whether launch/drain ramp has a
//     per-CTA component; wall time has been pinned at ~6.64us for 4 rounds.

#define BB 8
#define C_IN 16
#define C_OUT 16
#define LL 1024
#define KK 8
#define L_OUT (LL - KK + 1)   // 1017
#define NQ 9

__global__ __launch_bounds__(LL) void DenseQConv1D_84542136255139_kernel(
    const float* __restrict__ x,      // [B, C_IN, L]
    const float* __restrict__ theta,  // [C_OUT, NQ]
    float* __restrict__ out)          // [B, C_OUT, L_OUT]
{
    __shared__ float a[LL];           // full channel-reduced square row
    __shared__ float cosv[C_OUT];

    const int b   = blockIdx.x;
    const int tid = threadIdx.x;

    if (tid < C_OUT) cosv[tid] = cosf(theta[tid * NQ]);

    // a[tid] = sum_c x[b,c,tid]^2 — 16 fully coalesced loads, 4-way tree.
    {
        const float* xb = x + (size_t)b * (C_IN * LL) + tid;
        float s0 = 0.f, s1 = 0.f, s2 = 0.f, s3 = 0.f;
        #pragma unroll
        for (int c = 0; c < C_IN; c += 4) {
            float v0 = xb[(c + 0) * LL];
            float v1 = xb[(c + 1) * LL];
            float v2 = xb[(c + 2) * LL];
            float v3 = xb[(c + 3) * LL];
            s0 = fmaf(v0, v0, s0);
            s1 = fmaf(v1, v1, s1);
            s2 = fmaf(v2, v2, s2);
            s3 = fmaf(v3, v3, s3);
        }
        a[tid] = (s0 + s1) + (s2 + s3);
    }
    __syncthreads();

    if (tid < L_OUT) {
        float se = (a[tid]     + a[tid + 2]) + (a[tid + 4] + a[tid + 6]);
        float so = (a[tid + 1] + a[tid + 3]) + (a[tid + 5] + a[tid + 7]);
        float r  = __fdividef(se - so, fmaxf(se + so, 1e-24f));
        float* ob = out + (size_t)b * (C_OUT * L_OUT) + tid;
        #pragma unroll
        for (int c = 0; c < C_OUT; ++c) {
            ob[c * L_OUT] = cosv[c] * r;
        }
    }
}

extern "C" void kernel_launch(void* const* d_in, const int* in_sizes, int n_in,
                              void* d_out, int out_size)
{
    // Resolve inputs by element count (robust to metadata ordering):
    //   x: 131072, theta: 144, entangle: 262144 (unused)
    const float* x = nullptr;
    const float* theta = nullptr;
    for (int i = 0; i < n_in; ++i) {
        if (in_sizes[i] == BB * C_IN * LL)      x     = (const float*)d_in[i];
        else if (in_sizes[i] == C_OUT * NQ)     theta = (const float*)d_in[i];
    }

    DenseQConv1D_84542136255139_kernel<<<BB, LL>>>(x, theta, (float*)d_out);
}

// round 6
// speedup vs baseline: 1.3413x; 1.3413x over previous
#include <cuda_runtime.h>

// DenseQConv1D analytic collapse (exact):
//   out[b,c,l] = cos(theta[c,0]) * (S_even - S_odd) / max(S_total, 1e-24)
//   with S_* = windowed 8-tap sums of a[b,l] = sum_cin x[b,cin,l]^2.
// Derivation: out = s^T (E R) S (E R)^T s ; R S R^T = H(theta0) (x) I^8 ;
// E = CNOT-ring permutation (linear over GF(2)); conjugated M_c is
// diag(+/-cos(theta[c,0])) on the 128-dim patch support, sign = (-1)^(j&1).
//
// R6: channel-split CTA — 64 CTAs (proven best grid) x 256 threads.
//     Two halves per CTA each own 8 input channels / 8 output channels for
//     the same 128 l-positions: per-thread loads 16->8, stores 16->8,
//     FMA tree one level shallower. Halves combine through smem partials.

#define BB 8
#define C_IN 16
#define C_OUT 16
#define LL 1024
#define KK 8
#define L_OUT (LL - KK + 1)   // 1017
#define TL 128                // l-positions per CTA
#define NT 256                // threads per CTA (2 halves x TL)
#define NQ 9

__global__ __launch_bounds__(NT) void DenseQConv1D_84542136255139_kernel(
    const float* __restrict__ x,      // [B, C_IN, L]
    const float* __restrict__ theta,  // [C_OUT, NQ]
    float* __restrict__ out)          // [B, C_OUT, L_OUT]
{
    __shared__ float p[2][TL + KK];   // per-half channel-reduced squares + halo
    __shared__ float cosv[C_OUT];

    const int b    = blockIdx.y;
    const int l0   = blockIdx.x * TL;
    const int tid  = threadIdx.x;
    const int lidx = tid & (TL - 1);  // l within tile
    const int half = tid >> 7;        // 0: channels 0..7, 1: channels 8..15

    if (tid < C_OUT) cosv[tid] = cosf(theta[tid * NQ]);

    // Phase 1: p[half][lidx] = sum over this half's 8 channels of x^2.
    // Halo (lidx<7): l+TL computed in the SAME instruction stream (R3 lesson:
    // keep all loads in one flight).
    {
        const int l = l0 + lidx;                       // always < LL
        const bool halo_ok = (lidx < KK - 1) && (l + TL < LL);
        const float* xb = x + (size_t)b * (C_IN * LL) + half * (8 * LL) + l;

        float m0 = 0.f, m1 = 0.f, m2 = 0.f, m3 = 0.f;
        float h0 = 0.f, h1 = 0.f, h2 = 0.f, h3 = 0.f;
        #pragma unroll
        for (int c = 0; c < 8; c += 4) {
            float v0 = xb[(c + 0) * LL];
            float v1 = xb[(c + 1) * LL];
            float v2 = xb[(c + 2) * LL];
            float v3 = xb[(c + 3) * LL];
            float w0 = halo_ok ? xb[(c + 0) * LL + TL] : 0.f;
            float w1 = halo_ok ? xb[(c + 1) * LL + TL] : 0.f;
            float w2 = halo_ok ? xb[(c + 2) * LL + TL] : 0.f;
            float w3 = halo_ok ? xb[(c + 3) * LL + TL] : 0.f;
            m0 = fmaf(v0, v0, m0);  m1 = fmaf(v1, v1, m1);
            m2 = fmaf(v2, v2, m2);  m3 = fmaf(v3, v3, m3);
            h0 = fmaf(w0, w0, h0);  h1 = fmaf(w1, w1, h1);
            h2 = fmaf(w2, w2, h2);  h3 = fmaf(w3, w3, h3);
        }
        p[half][lidx] = (m0 + m1) + (m2 + m3);
        if (lidx < KK - 1) p[half][lidx + TL] = (h0 + h1) + (h2 + h3);
    }
    __syncthreads();

    // Phase 2: both halves redundantly form the window ratio (reads both
    // partial rows, pipelined LDS), then each stores its own 8 channels.
    const int l = l0 + lidx;
    if (l < L_OUT) {
        float a0 = p[0][lidx]     + p[1][lidx];
        float a1 = p[0][lidx + 1] + p[1][lidx + 1];
        float a2 = p[0][lidx + 2] + p[1][lidx + 2];
        float a3 = p[0][lidx + 3] + p[1][lidx + 3];
        float a4 = p[0][lidx + 4] + p[1][lidx + 4];
        float a5 = p[0][lidx + 5] + p[1][lidx + 5];
        float a6 = p[0][lidx + 6] + p[1][lidx + 6];
        float a7 = p[0][lidx + 7] + p[1][lidx + 7];
        float se = (a0 + a2) + (a4 + a6);
        float so = (a1 + a3) + (a5 + a7);
        float r  = __fdividef(se - so, fmaxf(se + so, 1e-24f));

        float* ob = out + (size_t)b * (C_OUT * L_OUT) + half * (8 * L_OUT) + l;
        #pragma unroll
        for (int c = 0; c < 8; ++c) {
            ob[c * L_OUT] = cosv[half * 8 + c] * r;
        }
    }
}

extern "C" void kernel_launch(void* const* d_in, const int* in_sizes, int n_in,
                              void* d_out, int out_size)
{
    // Resolve inputs by element count (robust to metadata ordering):
    //   x: 131072, theta: 144, entangle: 262144 (unused)
    const float* x = nullptr;
    const float* theta = nullptr;
    for (int i = 0; i < n_in; ++i) {
        if (in_sizes[i] == BB * C_IN * LL)      x     = (const float*)d_in[i];
        else if (in_sizes[i] == C_OUT * NQ)     theta = (const float*)d_in[i];
    }

    dim3 grid((L_OUT + TL - 1) / TL, BB);   // 8 x 8 = 64 CTAs
    DenseQConv1D_84542136255139_kernel<<<grid, NT>>>(x, theta, (float*)d_out);
}

// round 8
// speedup vs baseline: 1.3478x; 1.0048x over previous
#include <cuda_runtime.h>

// DenseQConv1D analytic collapse (exact):
//   out[b,c,l] = cos(theta[c,0]) * (S_even - S_odd) / max(S_total, 1e-24)
//   with S_* = windowed 8-tap sums of a[b,l] = sum_cin x[b,cin,l]^2.
// Derivation: out = s^T (E R) S (E R)^T s ; R S R^T = H(theta0) (x) I^8 ;
// E = CNOT-ring permutation (linear over GF(2)); conjugated M_c is
// diag(+/-cos(theta[c,0])) on the 128-dim patch support, sign = (-1)^(j&1).
//
// R8 = R7 resubmitted verbatim (R7 bench was an infra failure — container
//     died twice; kernel never ran). 4-way channel split: 64 CTAs (proven
//     best grid) x 512 threads, four quarters per CTA each owning 4 in/out
//     channels for the same 128 l-positions. Per-thread loads 4(+halo),
//     stores 4, FMA tree 2 levels. Quarters combine via smem partials.
//     Wall clock sits at the graph-replay floor (~6.6us); this banks margin.

#define BB 8
#define C_IN 16
#define C_OUT 16
#define LL 1024
#define KK 8
#define L_OUT (LL - KK + 1)   // 1017
#define TL 128                // l-positions per CTA
#define NT 512                // threads per CTA (4 quarters x TL)
#define NQ 9

__global__ __launch_bounds__(NT) void DenseQConv1D_84542136255139_kernel(
    const float* __restrict__ x,      // [B, C_IN, L]
    const float* __restrict__ theta,  // [C_OUT, NQ]
    float* __restrict__ out)          // [B, C_OUT, L_OUT]
{
    __shared__ float p[4][TL + KK];   // per-quarter channel-reduced squares + halo
    __shared__ float cosv[C_OUT];

    const int b    = blockIdx.y;
    const int l0   = blockIdx.x * TL;
    const int tid  = threadIdx.x;
    const int lidx = tid & (TL - 1);  // l within tile
    const int q    = tid >> 7;        // quarter: channels 4q .. 4q+3

    if (tid < C_OUT) cosv[tid] = cosf(theta[tid * NQ]);

    // Phase 1: p[q][lidx] = sum over this quarter's 4 channels of x^2.
    // Halo values computed in the same instruction stream (single load flight).
    {
        const int l = l0 + lidx;                       // always < LL
        const bool halo_ok = (lidx < KK - 1) && (l + TL < LL);
        const float* xb = x + (size_t)b * (C_IN * LL) + q * (4 * LL) + l;

        float v0 = xb[0 * LL];
        float v1 = xb[1 * LL];
        float v2 = xb[2 * LL];
        float v3 = xb[3 * LL];
        float w0 = halo_ok ? xb[0 * LL + TL] : 0.f;
        float w1 = halo_ok ? xb[1 * LL + TL] : 0.f;
        float w2 = halo_ok ? xb[2 * LL + TL] : 0.f;
        float w3 = halo_ok ? xb[3 * LL + TL] : 0.f;

        float m01 = fmaf(v0, v0, v1 * v1);
        float m23 = fmaf(v2, v2, v3 * v3);
        float h01 = fmaf(w0, w0, w1 * w1);
        float h23 = fmaf(w2, w2, w3 * w3);

        p[q][lidx] = m01 + m23;
        if (lidx < KK - 1) p[q][lidx + TL] = h01 + h23;
    }
    __syncthreads();

    // Phase 2: all quarters redundantly form the window ratio (32 pipelined
    // LDS), then each stores its own 4 output channels.
    const int l = l0 + lidx;
    if (l < L_OUT) {
        float a0 = (p[0][lidx]     + p[1][lidx])     + (p[2][lidx]     + p[3][lidx]);
        float a1 = (p[0][lidx + 1] + p[1][lidx + 1]) + (p[2][lidx + 1] + p[3][lidx + 1]);
        float a2 = (p[0][lidx + 2] + p[1][lidx + 2]) + (p[2][lidx + 2] + p[3][lidx + 2]);
        float a3 = (p[0][lidx + 3] + p[1][lidx + 3]) + (p[2][lidx + 3] + p[3][lidx + 3]);
        float a4 = (p[0][lidx + 4] + p[1][lidx + 4]) + (p[2][lidx + 4] + p[3][lidx + 4]);
        float a5 = (p[0][lidx + 5] + p[1][lidx + 5]) + (p[2][lidx + 5] + p[3][lidx + 5]);
        float a6 = (p[0][lidx + 6] + p[1][lidx + 6]) + (p[2][lidx + 6] + p[3][lidx + 6]);
        float a7 = (p[0][lidx + 7] + p[1][lidx + 7]) + (p[2][lidx + 7] + p[3][lidx + 7]);
        float se = (a0 + a2) + (a4 + a6);
        float so = (a1 + a3) + (a5 + a7);
        float r  = __fdividef(se - so, fmaxf(se + so, 1e-24f));

        float* ob = out + (size_t)b * (C_OUT * L_OUT) + q * (4 * L_OUT) + l;
        #pragma unroll
        for (int c = 0; c < 4; ++c) {
            ob[c * L_OUT] = cosv[q * 4 + c] * r;
        }
    }
}

extern "C" void kernel_launch(void* const* d_in, const int* in_sizes, int n_in,
                              void* d_out, int out_size)
{
    // Resolve inputs by element count (robust to metadata ordering):
    //   x: 131072, theta: 144, entangle: 262144 (unused)
    const float* x = nullptr;
    const float* theta = nullptr;
    for (int i = 0; i < n_in; ++i) {
        if (in_sizes[i] == BB * C_IN * LL)      x     = (const float*)d_in[i];
        else if (in_sizes[i] == C_OUT * NQ)     theta = (const float*)d_in[i];
    }

    dim3 grid((L_OUT + TL - 1) / TL, BB);   // 8 x 8 = 64 CTAs
    DenseQConv1D_84542136255139_kernel<<<grid, NT>>>(x, theta, (float*)d_out);
}